// round 7
// baseline (speedup 1.0000x reference)
#include <cuda_runtime.h>
#include <cuda_bf16.h>

#define NSP 8192
#define NR  2097152
#define NREP 64                      // scratch replicas for product-side REDG

__device__ float g_scratch[NREP * NSP];   // 2 MB static scratch (allowed)

__device__ __forceinline__ float ex2_approx(float x) {
    float y;
    asm("ex2.approx.ftz.f32 %0, %1;" : "=f"(y) : "f"(x));
    return y;
}

// Zero both the output and the scratch replicas.
__global__ void zero_kernel(float* __restrict__ out, int out_n) {
    int i = blockIdx.x * blockDim.x + threadIdx.x;
    if (i < out_n) out[i] = 0.0f;
    for (int j = i; j < NREP * NSP; j += gridDim.x * blockDim.x)
        g_scratch[j] = 0.0f;
}

// Fold the 64 scratch replicas into out (runs after the main kernel; scratch
// lines are L2-resident from the atomics).
__global__ void reduce_kernel(float* __restrict__ out) {
    const int i = blockIdx.x * blockDim.x + threadIdx.x;   // 8192 threads
    float s = 0.0f;
    #pragma unroll 8
    for (int r = 0; r < NREP; r++)
        s += g_scratch[r * NSP + i];
    out[i] += s;
}

struct Rxn {
    float a, b, g;
    int   t;
    int2  sp;
    int4  rw;
};

__global__ __launch_bounds__(512, 2)
void rates_scatter_kernel(
    const float* __restrict__ abund,
    const float* __restrict__ Tptr,
    const float* __restrict__ crptr,
    const float* __restrict__ fuvptr,
    const float* __restrict__ alpha,
    const float* __restrict__ beta,
    const float* __restrict__ gamma,
    const int*   __restrict__ rtype,
    const int2*  __restrict__ rspec,
    const int4*  __restrict__ rows4,
    float* __restrict__ out)
{
    extern __shared__ float smem[];
    float* acc = smem;          // [NSP] per-CTA reactant accumulator (smem ATOMS)
    float* sab = smem + NSP;    // [NSP] staged abundances (LDS gathers)

    for (int i = threadIdx.x; i < NSP; i += blockDim.x) {
        acc[i] = 0.0f;
        sab[i] = abund[i];
    }
    __syncthreads();

    // Product-side target: this CTA's scratch replica (only ~5 CTAs share one
    // replica -> ~8 colliding updates per address at the LTS atomic ALUs).
    float* rep = g_scratch + (size_t)(blockIdx.x & (NREP - 1)) * NSP;

    const float T   = *Tptr;
    const float cr  = *crptr;
    const float fuv = *fuvptr;
    const float L2E = 1.4426950408889634f;           // log2(e)
    const float c1  = __log2f(T * (1.0f / 300.0f));  // log2(T/300)
    const float c2  = -L2E / T;                      // exp(-g/T) = exp2(g*c2)

    const int stride = gridDim.x * blockDim.x;
    int r = blockIdx.x * blockDim.x + threadIdx.x;

    Rxn cur;
    if (r < NR) {
        cur.a = alpha[r]; cur.b = beta[r]; cur.g = gamma[r];
        cur.t = rtype[r]; cur.sp = rspec[r]; cur.rw = rows4[r];
    }

    while (r < NR) {
        const int rn = r + stride;

        // Prefetch next iteration's streaming loads.
        Rxn nxt;
        if (rn < NR) {
            nxt.a = alpha[rn]; nxt.b = beta[rn]; nxt.g = gamma[rn];
            nxt.t = rtype[rn]; nxt.sp = rspec[rn]; nxt.rw = rows4[rn];
        }

        {
            const float e  = (cur.t == 0) ? fmaf(cur.b, c1, cur.g * c2)
                                          : (-cur.g * L2E);
            const float ex = ex2_approx(e);
            float k;
            if (cur.t == 1)      k = cur.a * cr;
            else if (cur.t == 2) k = cur.a * fuv * ex;
            else                 k = cur.a * ex;

            k *= sab[cur.sp.x] * sab[cur.sp.y];

            // Split the scatter across the two atomic pipes:
            atomicAdd(&acc[cur.rw.x], -k);    // smem ATOMS
            atomicAdd(&acc[cur.rw.y], -k);    // smem ATOMS
            atomicAdd(&rep[cur.rw.z],  k);    // L2 REDG (no-return, replicated)
            atomicAdd(&rep[cur.rw.w],  k);    // L2 REDG
        }

        cur = nxt;
        r = rn;
    }

    __syncthreads();
    for (int i = threadIdx.x; i < NSP; i += blockDim.x)
        atomicAdd(&out[i], acc[i]);   // 296-way flush (proven cheap)
}

extern "C" void kernel_launch(void* const* d_in, const int* in_sizes, int n_in,
                              void* d_out, int out_size) {
    const float* abund  = (const float*)d_in[0];
    const float* T      = (const float*)d_in[1];
    const float* crr    = (const float*)d_in[2];
    const float* fuvr   = (const float*)d_in[3];
    float* out = (float*)d_out;

    const int smem_bytes = 2 * NSP * sizeof(float);  // 64 KB
    cudaFuncSetAttribute(rates_scatter_kernel,
                         cudaFuncAttributeMaxDynamicSharedMemorySize, smem_bytes);

    zero_kernel<<<(NREP * NSP + 1023) / 1024, 1024>>>(out, out_size);

    rates_scatter_kernel<<<296, 512, smem_bytes>>>(
        abund, T, crr, fuvr,
        (const float*)d_in[4], (const float*)d_in[5], (const float*)d_in[6],
        (const int*)d_in[7], (const int2*)d_in[8], (const int4*)d_in[9],
        out);

    reduce_kernel<<<NSP / 256, 256>>>(out);
}

// round 8
// speedup vs baseline: 1.0571x; 1.0571x over previous
#include <cuda_runtime.h>
#include <cuda_bf16.h>

#define NSP 8192
#define NR  2097152
#define NREPL 4   // smem accumulator replicas (one per SMSP)

// Shared layout: acc[4][NSP] then sab[NSP]  => 160 KB
#define SMEM_FLOATS (NREPL * NSP + NSP)

__device__ __forceinline__ float ex2_approx(float x) {
    float y;
    asm("ex2.approx.ftz.f32 %0, %1;" : "=f"(y) : "f"(x));
    return y;
}

__global__ void zero_out_kernel(float* __restrict__ out, int n) {
    int i = blockIdx.x * blockDim.x + threadIdx.x;
    if (i < n) out[i] = 0.0f;
}

struct Rxn {
    float a, b, g;
    int   t;
    int2  sp;
    int4  rw;
};

__global__ __launch_bounds__(1024, 1)
void rates_scatter_kernel(
    const float* __restrict__ abund,
    const float* __restrict__ Tptr,
    const float* __restrict__ crptr,
    const float* __restrict__ fuvptr,
    const float* __restrict__ alpha,
    const float* __restrict__ beta,
    const float* __restrict__ gamma,
    const int*   __restrict__ rtype,
    const int2*  __restrict__ rspec,
    const int4*  __restrict__ rows4,
    float* __restrict__ out)
{
    extern __shared__ float smem[];
    float* accs = smem;                  // [NREPL][NSP]
    float* sab  = smem + NREPL * NSP;    // [NSP] staged abundances

    for (int i = threadIdx.x; i < NREPL * NSP; i += blockDim.x) accs[i] = 0.0f;
    for (int i = threadIdx.x; i < NSP; i += blockDim.x) sab[i] = abund[i];
    __syncthreads();

    // Each warp scatters into the replica matching its SMSP (warp & 3):
    // warps on different SMSPs never collide on an address.
    float* acc = accs + ((threadIdx.x >> 5) & (NREPL - 1)) * NSP;

    const float T   = *Tptr;
    const float cr  = *crptr;
    const float fuv = *fuvptr;
    const float L2E = 1.4426950408889634f;           // log2(e)
    const float c1  = __log2f(T * (1.0f / 300.0f));  // log2(T/300)
    const float c2  = -L2E / T;                      // exp(-g/T) = exp2(g*c2)

    const int stride = gridDim.x * blockDim.x;
    int r = blockIdx.x * blockDim.x + threadIdx.x;

    Rxn cur;
    if (r < NR) {
        cur.a = alpha[r]; cur.b = beta[r]; cur.g = gamma[r];
        cur.t = rtype[r]; cur.sp = rspec[r]; cur.rw = rows4[r];
    }

    while (r < NR) {
        const int rn = r + stride;

        // Prefetch next iteration's streaming loads (hide DRAM latency).
        Rxn nxt;
        if (rn < NR) {
            nxt.a = alpha[rn]; nxt.b = beta[rn]; nxt.g = gamma[rn];
            nxt.t = rtype[rn]; nxt.sp = rspec[rn]; nxt.rw = rows4[rn];
        }

        {
            const float e  = (cur.t == 0) ? fmaf(cur.b, c1, cur.g * c2)
                                          : (-cur.g * L2E);
            const float ex = ex2_approx(e);
            float k;
            if (cur.t == 1)      k = cur.a * cr;
            else if (cur.t == 2) k = cur.a * fuv * ex;
            else                 k = cur.a * ex;

            k *= sab[cur.sp.x] * sab[cur.sp.y];

            atomicAdd(&acc[cur.rw.x], -k);
            atomicAdd(&acc[cur.rw.y], -k);
            atomicAdd(&acc[cur.rw.z],  k);
            atomicAdd(&acc[cur.rw.w],  k);
        }

        cur = nxt;
        r = rn;
    }

    __syncthreads();
    // Fold replicas and flush once per element per CTA.
    for (int i = threadIdx.x; i < NSP; i += blockDim.x) {
        const float s = accs[i] + accs[NSP + i] + accs[2 * NSP + i] + accs[3 * NSP + i];
        atomicAdd(&out[i], s);   // no-return -> REDG
    }
}

extern "C" void kernel_launch(void* const* d_in, const int* in_sizes, int n_in,
                              void* d_out, int out_size) {
    const float* abund  = (const float*)d_in[0];
    const float* T      = (const float*)d_in[1];
    const float* crr    = (const float*)d_in[2];
    const float* fuvr   = (const float*)d_in[3];
    float* out = (float*)d_out;

    const int smem_bytes = SMEM_FLOATS * sizeof(float);   // 160 KB
    cudaFuncSetAttribute(rates_scatter_kernel,
                         cudaFuncAttributeMaxDynamicSharedMemorySize, smem_bytes);

    zero_out_kernel<<<(out_size + 255) / 256, 256>>>(out, out_size);

    rates_scatter_kernel<<<148, 1024, smem_bytes>>>(
        abund, T, crr, fuvr,
        (const float*)d_in[4], (const float*)d_in[5], (const float*)d_in[6],
        (const int*)d_in[7], (const int2*)d_in[8], (const int4*)d_in[9],
        out);
}

// round 9
// speedup vs baseline: 1.1872x; 1.1231x over previous
#include <cuda_runtime.h>
#include <cuda_bf16.h>

#define NSP 8192
#define NR  2097152
#define NCTA 296

__device__ float g_partial[NCTA * NSP];   // 9.7 MB static scratch (fully overwritten each call)

__device__ __forceinline__ float ex2_approx(float x) {
    float y;
    asm("ex2.approx.ftz.f32 %0, %1;" : "=f"(y) : "f"(x));
    return y;
}

__device__ __forceinline__ void red_shared_add(float* p, float v) {
    asm volatile("red.shared.add.f32 [%0], %1;"
                 :: "l"(__cvta_generic_to_shared(p)), "f"(v) : "memory");
}

struct Rxn {
    float a, b, g;
    int   t;
    int2  sp;
    int4  rw;
};

__global__ __launch_bounds__(512, 2)
void rates_scatter_kernel(
    const float* __restrict__ abund,
    const float* __restrict__ Tptr,
    const float* __restrict__ crptr,
    const float* __restrict__ fuvptr,
    const float* __restrict__ alpha,
    const float* __restrict__ beta,
    const float* __restrict__ gamma,
    const int*   __restrict__ rtype,
    const int2*  __restrict__ rspec,
    const int4*  __restrict__ rows4)
{
    extern __shared__ float smem[];
    float* acc = smem;          // [NSP] per-CTA accumulator
    float* sab = smem + NSP;    // [NSP] staged abundances

    for (int i = threadIdx.x; i < NSP; i += blockDim.x) {
        acc[i] = 0.0f;
        sab[i] = abund[i];
    }
    __syncthreads();

    const float T   = *Tptr;
    const float cr  = *crptr;
    const float fuv = *fuvptr;
    const float L2E = 1.4426950408889634f;           // log2(e)
    const float c1  = __log2f(T * (1.0f / 300.0f));  // log2(T/300)
    const float c2  = -L2E / T;                      // exp(-g/T) = exp2(g*c2)

    const int stride = gridDim.x * blockDim.x;
    int r = blockIdx.x * blockDim.x + threadIdx.x;

    Rxn cur;
    if (r < NR) {
        cur.a = alpha[r]; cur.b = beta[r]; cur.g = gamma[r];
        cur.t = rtype[r]; cur.sp = rspec[r]; cur.rw = rows4[r];
    }

    while (r < NR) {
        const int rn = r + stride;

        // Prefetch next iteration's streaming loads (hides DRAM latency
        // behind this iteration's atomic work).
        Rxn nxt;
        if (rn < NR) {
            nxt.a = alpha[rn]; nxt.b = beta[rn]; nxt.g = gamma[rn];
            nxt.t = rtype[rn]; nxt.sp = rspec[rn]; nxt.rw = rows4[rn];
        }

        {
            const float e  = (cur.t == 0) ? fmaf(cur.b, c1, cur.g * c2)
                                          : (-cur.g * L2E);
            const float ex = ex2_approx(e);
            float k;
            if (cur.t == 1)      k = cur.a * cr;
            else if (cur.t == 2) k = cur.a * fuv * ex;
            else                 k = cur.a * ex;

            k *= sab[cur.sp.x] * sab[cur.sp.y];

            red_shared_add(&acc[cur.rw.x], -k);   // no-return REDS
            red_shared_add(&acc[cur.rw.y], -k);
            red_shared_add(&acc[cur.rw.z],  k);
            red_shared_add(&acc[cur.rw.w],  k);
        }

        cur = nxt;
        r = rn;
    }

    __syncthreads();
    // Plain coalesced stores — no atomic contention, no pre-zeroed output needed.
    float* mine = g_partial + (size_t)blockIdx.x * NSP;
    for (int i = threadIdx.x; i < NSP; i += blockDim.x)
        mine[i] = acc[i];
}

// out[i] = sum over the 296 per-CTA partials; overwrites out (poison-safe).
__global__ __launch_bounds__(256, 4)
void reduce_kernel(float* __restrict__ out) {
    const int i = blockIdx.x * blockDim.x + threadIdx.x;   // 8192 threads
    float s0 = 0.f, s1 = 0.f, s2 = 0.f, s3 = 0.f;
    #pragma unroll 4
    for (int c = 0; c < NCTA; c += 4) {
        s0 += g_partial[(size_t)c * NSP + i];
        s1 += g_partial[(size_t)(c + 1) * NSP + i];
        s2 += g_partial[(size_t)(c + 2) * NSP + i];
        s3 += g_partial[(size_t)(c + 3) * NSP + i];
    }
    out[i] = (s0 + s1) + (s2 + s3);
}

extern "C" void kernel_launch(void* const* d_in, const int* in_sizes, int n_in,
                              void* d_out, int out_size) {
    const float* abund  = (const float*)d_in[0];
    const float* T      = (const float*)d_in[1];
    const float* crr    = (const float*)d_in[2];
    const float* fuvr   = (const float*)d_in[3];
    float* out = (float*)d_out;

    const int smem_bytes = 2 * NSP * sizeof(float);  // 64 KB
    cudaFuncSetAttribute(rates_scatter_kernel,
                         cudaFuncAttributeMaxDynamicSharedMemorySize, smem_bytes);

    rates_scatter_kernel<<<NCTA, 512, smem_bytes>>>(
        abund, T, crr, fuvr,
        (const float*)d_in[4], (const float*)d_in[5], (const float*)d_in[6],
        (const int*)d_in[7], (const int2*)d_in[8], (const int4*)d_in[9]);

    reduce_kernel<<<NSP / 256, 256>>>(out);
}

// round 10
// speedup vs baseline: 1.4606x; 1.2303x over previous
#include <cuda_runtime.h>
#include <cuda_bf16.h>

#define NSP 8192
#define NR  2097152
#define NCTA 296
#define RCHUNK 37          // 296 = 8 * 37 exactly

__device__ float g_partial[NCTA * NSP];   // 9.7 MB static scratch, overwritten each call

__device__ __forceinline__ float ex2_approx(float x) {
    float y;
    asm("ex2.approx.ftz.f32 %0, %1;" : "=f"(y) : "f"(x));
    return y;
}

__device__ __forceinline__ void red_shared_add(float* p, float v) {
    asm volatile("red.shared.add.f32 [%0], %1;"
                 :: "l"(__cvta_generic_to_shared(p)), "f"(v) : "memory");
}

struct Rxn {
    float a, b, g;
    int   t;
    int2  sp;
    int4  rw;
};

__global__ __launch_bounds__(512, 2)
void rates_scatter_kernel(
    const float* __restrict__ abund,
    const float* __restrict__ Tptr,
    const float* __restrict__ crptr,
    const float* __restrict__ fuvptr,
    const float* __restrict__ alpha,
    const float* __restrict__ beta,
    const float* __restrict__ gamma,
    const int*   __restrict__ rtype,
    const int2*  __restrict__ rspec,
    const int4*  __restrict__ rows4,
    float* __restrict__ out)
{
    extern __shared__ float smem[];
    float* acc = smem;          // [NSP] per-CTA accumulator
    float* sab = smem + NSP;    // [NSP] staged abundances

    for (int i = threadIdx.x; i < NSP; i += blockDim.x) {
        acc[i] = 0.0f;
        sab[i] = abund[i];
    }
    // Zero the (poisoned) output here; reduce_kernel's atomics run only after
    // this kernel fully completes (stream order), so this is race-free.
    if (blockIdx.x == 0)
        for (int i = threadIdx.x; i < NSP; i += blockDim.x) out[i] = 0.0f;
    __syncthreads();

    const float T   = *Tptr;
    const float cr  = *crptr;
    const float fuv = *fuvptr;
    const float L2E = 1.4426950408889634f;           // log2(e)
    const float c1  = __log2f(T * (1.0f / 300.0f));  // log2(T/300)
    const float c2  = -L2E / T;                      // exp(-g/T) = exp2(g*c2)

    const int stride = gridDim.x * blockDim.x;
    int r = blockIdx.x * blockDim.x + threadIdx.x;

    Rxn cur;
    if (r < NR) {
        cur.a = alpha[r]; cur.b = beta[r]; cur.g = gamma[r];
        cur.t = rtype[r]; cur.sp = rspec[r]; cur.rw = rows4[r];
    }

    while (r < NR) {
        const int rn = r + stride;

        // Prefetch next iteration's streaming loads.
        Rxn nxt;
        if (rn < NR) {
            nxt.a = alpha[rn]; nxt.b = beta[rn]; nxt.g = gamma[rn];
            nxt.t = rtype[rn]; nxt.sp = rspec[rn]; nxt.rw = rows4[rn];
        }

        {
            const float e  = (cur.t == 0) ? fmaf(cur.b, c1, cur.g * c2)
                                          : (-cur.g * L2E);
            const float ex = ex2_approx(e);
            float k;
            if (cur.t == 1)      k = cur.a * cr;
            else if (cur.t == 2) k = cur.a * fuv * ex;
            else                 k = cur.a * ex;

            k *= sab[cur.sp.x] * sab[cur.sp.y];

            red_shared_add(&acc[cur.rw.x], -k);   // no-return REDS (the key win)
            red_shared_add(&acc[cur.rw.y], -k);
            red_shared_add(&acc[cur.rw.z],  k);
            red_shared_add(&acc[cur.rw.w],  k);
        }

        cur = nxt;
        r = rn;
    }

    __syncthreads();
    float* mine = g_partial + (size_t)blockIdx.x * NSP;
    for (int i = threadIdx.x; i < NSP; i += blockDim.x)
        mine[i] = acc[i];     // plain coalesced STG, no contention
}

// Parallel fold: grid (NSP/256, 8). CTA (bx, by) sums rows [37*by, 37*(by+1))
// for its 256-species column chunk, then one REDG per element (8 per address).
__global__ __launch_bounds__(256, 8)
void reduce_kernel(float* __restrict__ out) {
    const int i  = blockIdx.x * blockDim.x + threadIdx.x;
    const int c0 = blockIdx.y * RCHUNK;
    const float* p = g_partial + (size_t)c0 * NSP + i;

    float s0 = 0.f, s1 = 0.f, s2 = 0.f, s3 = 0.f;
    #pragma unroll
    for (int c = 0; c < RCHUNK - 1; c += 4) {       // 36 rows, 4-deep MLP
        s0 += p[(size_t)c * NSP];
        s1 += p[(size_t)(c + 1) * NSP];
        s2 += p[(size_t)(c + 2) * NSP];
        s3 += p[(size_t)(c + 3) * NSP];
    }
    s0 += p[(size_t)(RCHUNK - 1) * NSP];            // row 36
    atomicAdd(&out[i], (s0 + s1) + (s2 + s3));      // no-return REDG
}

extern "C" void kernel_launch(void* const* d_in, const int* in_sizes, int n_in,
                              void* d_out, int out_size) {
    const float* abund  = (const float*)d_in[0];
    const float* T      = (const float*)d_in[1];
    const float* crr    = (const float*)d_in[2];
    const float* fuvr   = (const float*)d_in[3];
    float* out = (float*)d_out;

    const int smem_bytes = 2 * NSP * sizeof(float);  // 64 KB
    cudaFuncSetAttribute(rates_scatter_kernel,
                         cudaFuncAttributeMaxDynamicSharedMemorySize, smem_bytes);

    rates_scatter_kernel<<<NCTA, 512, smem_bytes>>>(
        abund, T, crr, fuvr,
        (const float*)d_in[4], (const float*)d_in[5], (const float*)d_in[6],
        (const int*)d_in[7], (const int2*)d_in[8], (const int4*)d_in[9],
        out);

    reduce_kernel<<<dim3(NSP / 256, 8), 256>>>(out);
}